// round 1
// baseline (speedup 1.0000x reference)
#include <cuda_runtime.h>
#include <cstdint>

// ---------------------------------------------------------------------------
// BaseGCN: kNN adjacency -> normalized Laplacian L = I - D^-1/2 A D^-1/2
// Shapes: x (4, 4096, 3) fp32, k=20 -> out (4, 4096, 4096) fp32.
// Since every row of A has exactly k ones, deg == k everywhere and
//   out[g, j] = (j==i ? 1 : 0) - (1/k) * [j in knn(i)].
// One CTA (256 thr) handles 8 rows of one batch:
//   stage all 4096 points as float4{x,y,z,|x|^2} in smem,
//   pass1: per-thread minima of shifted key s_j = |x_j|^2 - 2 x_i . x_j,
//   rank-(k+4) of 256 thread-minima via bit bisection -> safe threshold,
//   pass2: collect all s <= T into per-row buffer (~25 expected, cap 128),
//   warp-per-row: k extraction rounds on 64-bit (s_bits, j) keys
//   (lexicographic => lowest-index tie-break, matching lax.top_k),
//   then write the full 16KB row: zeros + scatter -1/k and diagonal.
// ---------------------------------------------------------------------------

constexpr int NN   = 4096;
constexpr int ROWS = 8;      // rows per CTA == warps per CTA
constexpr int NT   = 256;
constexpr int CPT  = NN / NT;   // 16 candidates per thread
constexpr int CAP  = 128;       // candidate buffer per row

// dynamic smem layout (bytes)
constexpr int SMEM_PTS  = 0;                    // float4 sp[4096]  = 65536
constexpr int SMEM_OVL  = 65536;                // tmin[8][256] f32 OR cand[8][128] u64 = 8192
constexpr int SMEM_KNN  = SMEM_OVL + 8192;      // int knn[8][32]   = 1024
constexpr int SMEM_MISC = SMEM_KNN + 1024;      // cnt/tbits/active/active_any
constexpr int SMEM_TOTAL = SMEM_MISC + 256;     // 75264 B

__device__ __forceinline__ unsigned f2ord(float f) {
    unsigned b = __float_as_uint(f);
    return b ^ ((b & 0x80000000u) ? 0xFFFFFFFFu : 0x80000000u);
}
__device__ __forceinline__ float ord2f(unsigned u) {
    unsigned b = (u & 0x80000000u) ? (u ^ 0x80000000u) : ~u;
    return __uint_as_float(b);
}
__device__ __forceinline__ unsigned long long umin64(unsigned long long a,
                                                     unsigned long long b) {
    return a < b ? a : b;
}

extern "C" __global__ void __launch_bounds__(NT, 3)
gcn_knn_lap(const float* __restrict__ x, const int* __restrict__ kptr,
            float* __restrict__ out) {
    extern __shared__ unsigned char smem_raw[];
    float4* sp = reinterpret_cast<float4*>(smem_raw + SMEM_PTS);
    float (*tmin)[NT] = reinterpret_cast<float(*)[NT]>(smem_raw + SMEM_OVL);
    unsigned long long (*cand)[CAP] =
        reinterpret_cast<unsigned long long(*)[CAP]>(smem_raw + SMEM_OVL);
    int (*knn)[32] = reinterpret_cast<int(*)[32]>(smem_raw + SMEM_KNN);
    int*      cnt        = reinterpret_cast<int*>(smem_raw + SMEM_MISC);
    unsigned* tbits      = reinterpret_cast<unsigned*>(smem_raw + SMEM_MISC + 32);
    int*      active     = reinterpret_cast<int*>(smem_raw + SMEM_MISC + 64);
    int*      active_any = reinterpret_cast<int*>(smem_raw + SMEM_MISC + 96);

    const int tid   = threadIdx.x;
    const int lane  = tid & 31;
    const int w     = tid >> 5;
    const int row0  = blockIdx.x * ROWS;       // global row index
    const int batch = row0 >> 12;              // row0 / 4096
    const int i0    = row0 & (NN - 1);         // local row base within batch
    const float* xb = x + (size_t)batch * NN * 3;

    int kk = (kptr != nullptr) ? *kptr : 20;
    kk = max(1, min(kk, 32));

    // ---- stage points: float4 {x, y, z, |x|^2} ----
    for (int p = tid; p < NN; p += NT) {
        float a = xb[3 * p], b = xb[3 * p + 1], c = xb[3 * p + 2];
        sp[p] = make_float4(a, b, c, fmaf(a, a, fmaf(b, b, c * c)));
    }
    __syncthreads();

    // per-row constants: -2 * x_i
    float m2x[ROWS], m2y[ROWS], m2z[ROWS];
#pragma unroll
    for (int r = 0; r < ROWS; ++r) {
        float4 q = sp[i0 + r];
        m2x[r] = -2.0f * q.x; m2y[r] = -2.0f * q.y; m2z[r] = -2.0f * q.z;
    }

    // ---- pass 1: per-thread minima of shifted distance key ----
    float tm[ROWS];
#pragma unroll
    for (int r = 0; r < ROWS; ++r) tm[r] = 3.0e38f;
    for (int t = 0; t < CPT; ++t) {
        int j = t * NT + tid;
        float4 c = sp[j];
#pragma unroll
        for (int r = 0; r < ROWS; ++r) {
            float s = fmaf(c.x, m2x[r], fmaf(c.y, m2y[r], fmaf(c.z, m2z[r], c.w)));
            tm[r] = fminf(tm[r], s);
        }
    }
#pragma unroll
    for (int r = 0; r < ROWS; ++r) tmin[r][tid] = tm[r];
    __syncthreads();

    // ---- phase 2: warp w = row w, rank-(kk+4) of 256 minima by bisection ----
    {
        unsigned vb[8];
#pragma unroll
        for (int s = 0; s < 8; ++s) vb[s] = f2ord(tmin[w][lane * 8 + s]);
        const int rank = kk + 4;   // <= 36 <= 256
        unsigned lo = 0u, hi = 0xFFFFFFFFu;
        while (lo < hi) {
            unsigned mid = lo + ((hi - lo) >> 1);
            int cle = 0;
#pragma unroll
            for (int s = 0; s < 8; ++s) cle += (vb[s] <= mid) ? 1 : 0;
            cle = __reduce_add_sync(0xFFFFFFFFu, cle);
            if (cle >= rank) hi = mid; else lo = mid + 1;
        }
        if (lane == 0) { tbits[w] = lo; cnt[w] = 0; active[w] = 1; }
    }
    __syncthreads();

    // ---- phase 3: collect candidates <= threshold (retry is ~impossible) ----
    for (int attempt = 0; attempt < 4; ++attempt) {
        if (tid == 0) {
            int any = 0;
#pragma unroll
            for (int r = 0; r < ROWS; ++r) any |= active[r];
            *active_any = any;
        }
        __syncthreads();
        if (!*active_any) break;
        float thr[ROWS]; int act[ROWS];
#pragma unroll
        for (int r = 0; r < ROWS; ++r) { thr[r] = ord2f(tbits[r]); act[r] = active[r]; }
        for (int t = 0; t < CPT; ++t) {
            int j = t * NT + tid;
            float4 c = sp[j];
#pragma unroll
            for (int r = 0; r < ROWS; ++r) {
                if (!act[r]) continue;
                float s = fmaf(c.x, m2x[r], fmaf(c.y, m2y[r], fmaf(c.z, m2z[r], c.w)));
                if (s <= thr[r]) {
                    int pos = atomicAdd(&cnt[r], 1);
                    if (pos < CAP)
                        cand[r][pos] =
                            ((unsigned long long)f2ord(s) << 32) | (unsigned)j;
                }
            }
        }
        __syncthreads();
        if (tid < ROWS) {
            if (active[tid]) {
                if (cnt[tid] >= kk) {
                    active[tid] = 0;
                } else {  // raise threshold (statistically unreachable)
                    unsigned tb = tbits[tid];
                    tb = (tb > 0xFF000000u) ? 0xFF7FFFFFu : tb + 0x00800000u;
                    tbits[tid] = tb; cnt[tid] = 0;
                }
            }
        }
        __syncthreads();
    }

    // ---- phase 4: warp w extracts kk smallest keys; phase 5: write row ----
    {
        const int r = w;
        int c    = min(cnt[r], CAP);
        int ksel = min(kk, c);
        unsigned long long key[4];
#pragma unroll
        for (int s = 0; s < 4; ++s) {
            int m = lane + 32 * s;
            key[s] = (m < c) ? cand[r][m] : ~0ull;
        }
        for (int q = 0; q < ksel; ++q) {
            unsigned long long b = umin64(umin64(key[0], key[1]),
                                          umin64(key[2], key[3]));
#pragma unroll
            for (int off = 16; off; off >>= 1)
                b = umin64(b, __shfl_xor_sync(0xFFFFFFFFu, b, off));
            if (lane == 0) knn[r][q] = (int)(unsigned)b;
#pragma unroll
            for (int s = 0; s < 4; ++s) if (key[s] == b) key[s] = ~0ull;
        }
        __syncwarp();

        const int gi   = row0 + r;
        const int iloc = i0 + r;
        float* orf = out + (size_t)gi * NN;
        float4* orow = reinterpret_cast<float4*>(orf);
        const float4 z4 = make_float4(0.f, 0.f, 0.f, 0.f);
#pragma unroll 4
        for (int m = lane; m < NN / 4; m += 32) orow[m] = z4;
        __syncwarp();
        const float voff = -1.0f / (float)kk;
        int myj = (lane < ksel) ? knn[r][lane] : -1;
        unsigned found = __ballot_sync(0xFFFFFFFFu, myj == iloc);
        if (lane < ksel) orf[myj] = (myj == iloc) ? (1.0f + voff) : voff;
        if (lane == 31 && !found) orf[iloc] = 1.0f;
    }
}

extern "C" void kernel_launch(void* const* d_in, const int* in_sizes, int n_in,
                              void* d_out, int out_size) {
    const float* x   = (const float*)d_in[0];
    const int*   kpt = (n_in >= 2) ? (const int*)d_in[1] : nullptr;
    float*       out = (float*)d_out;

    int total_pts  = in_sizes[0] / 3;          // B * N
    int total_rows = total_pts;                // one output row per point
    int grid = total_rows / ROWS;              // 2048 for B=4, N=4096

    cudaFuncSetAttribute(gcn_knn_lap,
                         cudaFuncAttributeMaxDynamicSharedMemorySize, SMEM_TOTAL);
    gcn_knn_lap<<<grid, NT, SMEM_TOTAL>>>(x, kpt, out);
}